// round 2
// baseline (speedup 1.0000x reference)
#include <cuda_runtime.h>
#include <cuda_bf16.h>
#include <math.h>

// ---------------- problem constants ----------------
#define BS     256
#define CE     22      // EEG channels
#define T1     1000
#define D2     96      // EPOCHS*IN_SIZE
#define KW     12
#define T2     989     // T1 - KW + 1
#define EP     3
#define INS    32
#define PP     8
#define OUTS   16
#define NSWEEP 12

// ---------------- scratch (device globals; no cudaMalloc allowed) ----------------
__device__ float g_h1[BS * CE * T1];            // conv1 raw output
__device__ float g_h2[(size_t)BS * D2 * T2];    // conv2 raw output
__device__ float g_a1[CE],  g_c1[CE];           // BN1 scale/shift (bias-folded)
__device__ float g_a2[D2],  g_c2[D2];           // BN2 scale/shift
__device__ float g_S [BS * EP * INS * INS];     // covariance matrices
__device__ float g_Up[BS * EP * INS * PP];      // top-8 eigenvectors
__device__ float g_QQt[BS * EP * OUTS * OUTS];
__device__ float g_KKt[BS * EP * OUTS * OUTS];
__device__ float g_Vp [BS * OUTS * OUTS];       // only epoch m=2 is needed

// ================= conv1: 22x22 channel mix per (b,t) =================
__global__ void k_conv1(const float* __restrict__ x, const float* __restrict__ w1,
                        float* __restrict__ h1) {
    __shared__ float sW[CE * CE];
    int tid = threadIdx.x;
    for (int i = tid; i < CE * CE; i += 256) sW[i] = w1[i];
    __syncthreads();
    int idx = blockIdx.x * 256 + tid;         // exactly BS*T1 threads
    int b = idx / T1, t = idx - b * T1;
    float xv[CE];
#pragma unroll
    for (int c = 0; c < CE; c++) xv[c] = x[(b * CE + c) * T1 + t];
#pragma unroll
    for (int o = 0; o < CE; o++) {
        float s = 0.f;
#pragma unroll
        for (int c = 0; c < CE; c++) s = fmaf(xv[c], sW[o * CE + c], s);
        h1[(b * CE + o) * T1 + t] = s;
    }
}

// ================= BN stats (double accumulation), fold to a*x + c =================
__global__ void k_stats(const float* __restrict__ h, const float* __restrict__ gamma,
                        const float* __restrict__ beta, float* __restrict__ a,
                        float* __restrict__ c, int C, int L) {
    int ch = blockIdx.x, tid = threadIdx.x;
    double s = 0.0, s2 = 0.0;
    for (int b = 0; b < BS; b++) {
        const float* p = h + ((size_t)b * C + ch) * L;
        for (int t = tid; t < L; t += 256) {
            double v = (double)p[t];
            s += v; s2 += v * v;
        }
    }
    __shared__ double rs[256], rs2[256];
    rs[tid] = s; rs2[tid] = s2;
    __syncthreads();
    for (int off = 128; off > 0; off >>= 1) {
        if (tid < off) { rs[tid] += rs[tid + off]; rs2[tid] += rs2[tid + off]; }
        __syncthreads();
    }
    if (tid == 0) {
        double n   = (double)BS * (double)L;
        double mu  = rs[0] / n;
        double var = rs2[0] / n - mu * mu;
        double av  = (double)gamma[ch] / sqrt(var + 1e-5);
        a[ch] = (float)av;
        c[ch] = beta[ch] - (float)(mu * av);
    }
}

// ================= conv2: 96 out-ch, taps (22 x 12), fused BN1+ELU on input =================
__global__ void k_conv2(const float* __restrict__ h1, const float* __restrict__ w2,
                        const float* __restrict__ a1, const float* __restrict__ c1,
                        float* __restrict__ h2) {
    __shared__ float sIn[CE][140];        // 128 outputs + 11 halo + pad
    __shared__ float sW[24][264];         // 24 out-ch chunk of (22*12) taps
    int b = blockIdx.x;
    int t0 = blockIdx.y * 128;
    int tid = threadIdx.x;

    for (int i = tid; i < CE * 140; i += 256) {
        int cc = i / 140, j = i - cc * 140;
        int gt = t0 + j;
        float v = 0.f;
        if (gt < T1) {
            v = h1[(b * CE + cc) * T1 + gt];
            v = fmaf(v, a1[cc], c1[cc]);
            v = v > 0.f ? v : expm1f(v);
        }
        sIn[cc][j] = v;
    }

    int lane = tid & 31;
    int og   = tid >> 5;                  // 0..7 warp id -> 3 out-ch each
    for (int ob = 0; ob < D2; ob += 24) {
        __syncthreads();                  // protect sIn (1st iter) / sW reuse
        for (int i = tid; i < 24 * 264; i += 256) sW[i / 264][i % 264] = w2[ob * 264 + i];
        __syncthreads();

        float acc[3][4];
#pragma unroll
        for (int aa = 0; aa < 3; aa++)
#pragma unroll
            for (int bb = 0; bb < 4; bb++) acc[aa][bb] = 0.f;

        for (int cc = 0; cc < CE; cc++) {
#pragma unroll
            for (int k = 0; k < KW; k++) {
                float w0 = sW[og * 3 + 0][cc * KW + k];
                float w1v = sW[og * 3 + 1][cc * KW + k];
                float w2v = sW[og * 3 + 2][cc * KW + k];
#pragma unroll
                for (int tt = 0; tt < 4; tt++) {
                    float xv = sIn[cc][lane + 32 * tt + k];
                    acc[0][tt] = fmaf(w0, xv, acc[0][tt]);
                    acc[1][tt] = fmaf(w1v, xv, acc[1][tt]);
                    acc[2][tt] = fmaf(w2v, xv, acc[2][tt]);
                }
            }
        }
#pragma unroll
        for (int oo = 0; oo < 3; oo++) {
            int o = ob + og * 3 + oo;
#pragma unroll
            for (int tt = 0; tt < 4; tt++) {
                int t = t0 + lane + 32 * tt;
                if (t < T2) h2[((size_t)b * D2 + o) * T2 + t] = acc[oo][tt];
            }
        }
    }
}

// ================= Gram: S[b,m] = X X^T (32x32 over 989), fused BN2+ELU =================
__global__ void k_cov(const float* __restrict__ h2, const float* __restrict__ a2,
                      const float* __restrict__ c2, float* __restrict__ S) {
    __shared__ float sX[INS][193];        // odd row stride -> conflict-free
    int bm = blockIdx.x;
    int b = bm / EP, m = bm - b * EP;
    int tid = threadIdx.x;                // 1024 threads = (c,d)
    int cc = tid >> 5, dd = tid & 31;
    int ch = m * INS + cc;
    float av = a2[ch], cv = c2[ch];
    const float* row = h2 + ((size_t)b * D2 + ch) * T2;

    float acc = 0.f;
    for (int t0 = 0; t0 < T2; t0 += 192) {
        int len = min(192, T2 - t0);
        __syncthreads();
        for (int j = dd; j < len; j += 32) {
            float v = row[t0 + j];
            v = fmaf(v, av, cv);
            v = v > 0.f ? v : expm1f(v);
            sX[cc][j] = v;
        }
        __syncthreads();
        for (int j = 0; j < len; j++)
            acc = fmaf(sX[cc][j], sX[dd][j], acc);
    }
    S[bm * (INS * INS) + tid] = acc;
}

// ================= parallel two-sided Jacobi, 32x32 symmetric, top-8 eigvecs =================
__global__ void k_jacobi(const float* __restrict__ S, float* __restrict__ Up) {
    __shared__ float A[32][33], V[32][33];
    __shared__ float cs[16], sn[16];
    __shared__ int pps[16], qqs[16], sidx[8];
    int bm = blockIdx.x, tid = threadIdx.x;   // 256 threads

    for (int i = tid; i < 1024; i += 256) {
        int r = i >> 5, cc = i & 31;
        A[r][cc] = S[bm * 1024 + i];
        V[r][cc] = (r == cc) ? 1.f : 0.f;
    }
    __syncthreads();

    int g = tid >> 4, l = tid & 15;
    for (int sw = 0; sw < NSWEEP; sw++) {
        for (int r = 0; r < 31; r++) {
            if (tid < 16) {
                int p = (tid == 0) ? 0 : ((tid - 1 + r) % 31) + 1;
                int q = ((30 - tid + r) % 31) + 1;
                if (p > q) { int tmp = p; p = q; q = tmp; }
                float app = A[p][p], aqq = A[q][q], apq = A[p][q];
                float cv = 1.f, sv = 0.f;
                if (fabsf(apq) > 1e-36f) {
                    float tau = (aqq - app) / (2.f * apq);
                    float tt = (tau >= 0.f ? 1.f : -1.f) / (fabsf(tau) + sqrtf(1.f + tau * tau));
                    cv = rsqrtf(1.f + tt * tt);
                    sv = tt * cv;
                }
                cs[tid] = cv; sn[tid] = sv; pps[tid] = p; qqs[tid] = q;
            }
            __syncthreads();
            {   // row phase: A = J^T A (disjoint rows across pairs)
                float cv = cs[g], sv = sn[g];
                int p = pps[g], q = qqs[g];
#pragma unroll
                for (int jj = l; jj < 32; jj += 16) {
                    float ap = A[p][jj], aq = A[q][jj];
                    A[p][jj] = cv * ap - sv * aq;
                    A[q][jj] = sv * ap + cv * aq;
                }
            }
            __syncthreads();
            {   // col phase: A = A J; V = V J (disjoint cols across pairs)
                float cv = cs[g], sv = sn[g];
                int p = pps[g], q = qqs[g];
#pragma unroll
                for (int ii = l; ii < 32; ii += 16) {
                    float ap = A[ii][p], aq = A[ii][q];
                    A[ii][p] = cv * ap - sv * aq;
                    A[ii][q] = sv * ap + cv * aq;
                    float vp = V[ii][p], vq = V[ii][q];
                    V[ii][p] = cv * vp - sv * vq;
                    V[ii][q] = sv * vp + cv * vq;
                }
            }
            __syncthreads();
        }
    }

    if (tid == 0) {  // select 8 largest eigenvalues
        float vals[32];
        for (int i = 0; i < 32; i++) vals[i] = A[i][i];
        for (int j = 0; j < 8; j++) {
            int am = 0; float mv = vals[0];
            for (int i = 1; i < 32; i++) if (vals[i] > mv) { mv = vals[i]; am = i; }
            sidx[j] = am; vals[am] = -3.4e38f;
        }
    }
    __syncthreads();
    {
        int cc = tid >> 3, j = tid & 7;      // 256 threads = 32x8
        Up[bm * (INS * PP) + tid] = V[cc][sidx[j]];
    }
}

// ================= projectors: P = M (M^T M)^{-1} M^T via Cholesky, M = W @ Up =================
__global__ void k_proj(const float* __restrict__ Up, const float* __restrict__ wq,
                       const float* __restrict__ wk, const float* __restrict__ wv,
                       float* __restrict__ QQt, float* __restrict__ KKt,
                       float* __restrict__ Vp) {
    __shared__ float sUp[32][8], sM[16][8], sG[8][8], sY[16][8];
    int bm = blockIdx.x, tid = threadIdx.x;   // 128 threads
    int b = bm / EP, m = bm - b * EP;
    for (int i = tid; i < 256; i += 128) sUp[i >> 3][i & 7] = Up[bm * 256 + i];

    int nmat = (m == 2) ? 3 : 2;              // V-projector only needed at m=2
    for (int mat = 0; mat < nmat; mat++) {
        const float* W = (mat == 0) ? wq : (mat == 1) ? wk : wv;
        __syncthreads();
        {   // M = W (16x32) @ Up (32x8)
            int r = tid >> 3, p = tid & 7;
            float s = 0.f;
            for (int cc = 0; cc < 32; cc++) s = fmaf(W[r * 32 + cc], sUp[cc][p], s);
            sM[r][p] = s;
        }
        __syncthreads();
        if (tid < 64) {   // G = M^T M
            int i = tid >> 3, j = tid & 7;
            float s = 0.f;
            for (int rr = 0; rr < 16; rr++) s = fmaf(sM[rr][i], sM[rr][j], s);
            sG[i][j] = s;
        }
        __syncthreads();
        if (tid == 0) {   // Cholesky (lower) in place
            for (int k = 0; k < 8; k++) {
                float lkk = sqrtf(sG[k][k]);
                sG[k][k] = lkk;
                float inv = 1.f / lkk;
                for (int i = k + 1; i < 8; i++) sG[i][k] *= inv;
                for (int j = k + 1; j < 8; j++)
                    for (int i = j; i < 8; i++) sG[i][j] -= sG[i][k] * sG[j][k];
            }
        }
        __syncthreads();
        if (tid < 16) {   // Y^T rows: solve L y = M[r,:]^T
            int r = tid;
            for (int i = 0; i < 8; i++) {
                float v = sM[r][i];
                for (int j = 0; j < i; j++) v -= sG[i][j] * sY[r][j];
                sY[r][i] = v / sG[i][i];
            }
        }
        __syncthreads();
        float* outp = (mat == 0) ? (QQt + bm * 256)
                    : (mat == 1) ? (KKt + bm * 256)
                                 : (Vp + b * 256);
        for (int e = tid; e < 256; e += 128) {   // P = Y^T Y
            int u = e >> 4, v = e & 15;
            float s = 0.f;
#pragma unroll
            for (int i = 0; i < 8; i++) s = fmaf(sY[u][i], sY[v][i], s);
            outp[e] = s;
        }
    }
}

// ================= E, softmax weights, final linear =================
__global__ void k_final(const float* __restrict__ QQt, const float* __restrict__ KKt,
                        const float* __restrict__ Vp, const float* __restrict__ lw,
                        const float* __restrict__ lb, float* __restrict__ out) {
    int b = blockIdx.x, tid = threadIdx.x;    // 256 threads
    __shared__ float sQ[3 * 256], sK[3 * 256], sV[256];
    __shared__ float sE[9], swv[3];
    __shared__ float red[8];
    __shared__ float red12[12][8];
    for (int i = tid; i < 768; i += 256) {
        sQ[i] = QQt[b * 768 + i];
        sK[i] = KKt[b * 768 + i];
    }
    sV[tid] = Vp[b * 256 + tid];
    __syncthreads();

    int u = tid >> 4, v = tid & 15;
    for (int ij = 0; ij < 9; ij++) {
        int i = ij / 3, j = ij - 3 * i;
        const float* Qj = sQ + j * 256;
        const float* Ki = sK + i * 256;
        float dd = 0.f;
#pragma unroll
        for (int w = 0; w < 16; w++) {
            float du = Qj[u * 16 + w] - Ki[u * 16 + w];
            float dv = Qj[v * 16 + w] - Ki[v * 16 + w];
            dd = fmaf(du, dv, dd);
        }
        float val = dd * dd;
        for (int off = 16; off > 0; off >>= 1) val += __shfl_down_sync(0xffffffffu, val, off);
        if ((tid & 31) == 0) red[tid >> 5] = val;
        __syncthreads();
        if (tid == 0) {
            float s = 0.f;
            for (int w = 0; w < 8; w++) s += red[w];
            sE[ij] = sqrtf(s);
        }
        __syncthreads();
    }
    if (tid == 0) {
        for (int j = 0; j < 3; j++) {
            float s0 = 1.f / (1.f + log1pf(sE[0 * 3 + j]));
            float s1 = 1.f / (1.f + log1pf(sE[1 * 3 + j]));
            float s2 = 1.f / (1.f + log1pf(sE[2 * 3 + j]));
            float mx = fmaxf(s0, fmaxf(s1, s2));
            float e0 = expf(s0 - mx), e1 = expf(s1 - mx), e2 = expf(s2 - mx);
            swv[j] = e2 / (e0 + e1 + e2);
        }
    }
    __syncthreads();

    float vv = sV[tid];
    float part[12];
#pragma unroll
    for (int r = 0; r < 4; r++)
#pragma unroll
        for (int j = 0; j < 3; j++)
            part[r * 3 + j] = lw[r * 768 + j * 256 + tid] * vv;
#pragma unroll
    for (int kk = 0; kk < 12; kk++) {
        float val = part[kk];
        for (int off = 16; off > 0; off >>= 1) val += __shfl_down_sync(0xffffffffu, val, off);
        if ((tid & 31) == 0) red12[kk][tid >> 5] = val;
    }
    __syncthreads();
    if (tid < 4) {
        float o = lb[tid];
        for (int j = 0; j < 3; j++) {
            float ds = 0.f;
            for (int w = 0; w < 8; w++) ds += red12[tid * 3 + j][w];
            o = fmaf(swv[j], ds, o);
        }
        out[b * 4 + tid] = o;
    }
}

// ================= launch =================
extern "C" void kernel_launch(void* const* d_in, const int* in_sizes, int n_in,
                              void* d_out, int out_size) {
    const float* x      = (const float*)d_in[0];
    const float* conv1w = (const float*)d_in[1];
    // d_in[2] conv1_b: cancels inside BN exactly
    const float* bn1g   = (const float*)d_in[3];
    const float* bn1b   = (const float*)d_in[4];
    const float* conv2w = (const float*)d_in[5];
    // d_in[6] conv2_b: cancels inside BN exactly
    const float* bn2g   = (const float*)d_in[7];
    const float* bn2b   = (const float*)d_in[8];
    const float* wq     = (const float*)d_in[9];
    const float* wk     = (const float*)d_in[10];
    const float* wv     = (const float*)d_in[11];
    const float* linw   = (const float*)d_in[12];
    const float* linb   = (const float*)d_in[13];
    float* out = (float*)d_out;

    float *h1, *h2, *a1, *c1, *a2, *c2, *S, *Up, *QQt, *KKt, *Vp;
    cudaGetSymbolAddress((void**)&h1,  g_h1);
    cudaGetSymbolAddress((void**)&h2,  g_h2);
    cudaGetSymbolAddress((void**)&a1,  g_a1);
    cudaGetSymbolAddress((void**)&c1,  g_c1);
    cudaGetSymbolAddress((void**)&a2,  g_a2);
    cudaGetSymbolAddress((void**)&c2,  g_c2);
    cudaGetSymbolAddress((void**)&S,   g_S);
    cudaGetSymbolAddress((void**)&Up,  g_Up);
    cudaGetSymbolAddress((void**)&QQt, g_QQt);
    cudaGetSymbolAddress((void**)&KKt, g_KKt);
    cudaGetSymbolAddress((void**)&Vp,  g_Vp);

    k_conv1 <<<(BS * T1) / 256, 256>>>(x, conv1w, h1);
    k_stats <<<CE, 256>>>(h1, bn1g, bn1b, a1, c1, CE, T1);
    k_conv2 <<<dim3(BS, 8), 256>>>(h1, conv2w, a1, c1, h2);
    k_stats <<<D2, 256>>>(h2, bn2g, bn2b, a2, c2, D2, T2);
    k_cov   <<<BS * EP, 1024>>>(h2, a2, c2, S);
    k_jacobi<<<BS * EP, 256>>>(S, Up);
    k_proj  <<<BS * EP, 128>>>(Up, wq, wk, wv, QQt, KKt, Vp);
    k_final <<<BS, 256>>>(QQt, KKt, Vp, linw, linb, out);
}

// round 3
// speedup vs baseline: 1.6587x; 1.6587x over previous
#include <cuda_runtime.h>
#include <cuda_bf16.h>
#include <math.h>

// ---------------- problem constants ----------------
#define BS     256
#define CE     22      // EEG channels
#define T1     1000
#define D2     96      // EPOCHS*IN_SIZE
#define KW     12
#define T2     989     // T1 - KW + 1
#define EP     3
#define INS    32
#define PP     8
#define OUTS   16
#define NSWEEP 10
#define NB1    1000    // conv1 blocks
#define NB2    2048    // conv2 blocks

// ---------------- scratch ----------------
__device__ float g_h1[BS * CE * T1];
__device__ float g_h2[(size_t)BS * D2 * T2];
__device__ float g_a1[CE],  g_c1[CE];
__device__ float g_a2[D2],  g_c2[D2];
__device__ float g_S [BS * EP * INS * INS];
__device__ float g_Up[BS * EP * INS * PP];
__device__ float g_QQt[BS * EP * OUTS * OUTS];
__device__ float g_KKt[BS * EP * OUTS * OUTS];
__device__ float g_Vp [BS * OUTS * OUTS];
__device__ float g_ps1 [CE * NB1], g_ps1q[CE * NB1];
__device__ float g_ps2 [D2 * NB2], g_ps2q[D2 * NB2];

// ---------------- f32x2 helpers (Blackwell packed fp32) ----------------
__device__ __forceinline__ unsigned long long ffma2(unsigned long long a,
                                                    unsigned long long b,
                                                    unsigned long long c) {
    unsigned long long d;
    asm("fma.rn.f32x2 %0, %1, %2, %3;" : "=l"(d) : "l"(a), "l"(b), "l"(c));
    return d;
}
__device__ __forceinline__ unsigned long long pack2(float x) {
    unsigned long long r;
    asm("mov.b64 %0, {%1, %1};" : "=l"(r) : "f"(x));
    return r;
}
__device__ __forceinline__ void unpack2(unsigned long long v, float& lo, float& hi) {
    asm("mov.b64 {%0, %1}, %2;" : "=f"(lo), "=f"(hi) : "l"(v));
}

// ================= conv1 (22x22 mix) + fused BN1 partial stats =================
__global__ void k_conv1(const float* __restrict__ x, const float* __restrict__ w1,
                        float* __restrict__ h1, float* __restrict__ ps,
                        float* __restrict__ psq) {
    __shared__ float sW[CE * CE];
    __shared__ float wb[CE][8], wb2[CE][8];
    int tid = threadIdx.x;
    for (int i = tid; i < CE * CE; i += 256) sW[i] = w1[i];
    __syncthreads();
    int idx = blockIdx.x * 256 + tid;
    int b = idx / T1, t = idx - b * T1;
    int lane = tid & 31, wrp = tid >> 5;
    float xv[CE];
#pragma unroll
    for (int c = 0; c < CE; c++) xv[c] = x[(b * CE + c) * T1 + t];
#pragma unroll
    for (int o = 0; o < CE; o++) {
        float s = 0.f;
#pragma unroll
        for (int c = 0; c < CE; c++) s = fmaf(xv[c], sW[o * CE + c], s);
        h1[(b * CE + o) * T1 + t] = s;
        float v = s, v2 = s * s;
#pragma unroll
        for (int off = 16; off > 0; off >>= 1) {
            v  += __shfl_down_sync(0xffffffffu, v,  off);
            v2 += __shfl_down_sync(0xffffffffu, v2, off);
        }
        if (lane == 0) { wb[o][wrp] = v; wb2[o][wrp] = v2; }
    }
    __syncthreads();
    if (tid < CE) {
        float a = 0.f, bq = 0.f;
#pragma unroll
        for (int w = 0; w < 8; w++) { a += wb[tid][w]; bq += wb2[tid][w]; }
        ps [tid * NB1 + blockIdx.x] = a;
        psq[tid * NB1 + blockIdx.x] = bq;
    }
}

// ================= finalize BN: partials -> a*x + c =================
__global__ void k_fin(const float* __restrict__ ps, const float* __restrict__ psq,
                      const float* __restrict__ gamma, const float* __restrict__ beta,
                      float* __restrict__ a, float* __restrict__ c,
                      int NB, double n) {
    int ch = blockIdx.x, tid = threadIdx.x;
    double s = 0.0, s2 = 0.0;
    for (int i = tid; i < NB; i += 256) {
        s  += (double)ps [ch * NB + i];
        s2 += (double)psq[ch * NB + i];
    }
    __shared__ double rs[256], rs2[256];
    rs[tid] = s; rs2[tid] = s2;
    __syncthreads();
    for (int off = 128; off > 0; off >>= 1) {
        if (tid < off) { rs[tid] += rs[tid + off]; rs2[tid] += rs2[tid + off]; }
        __syncthreads();
    }
    if (tid == 0) {
        double mu  = rs[0] / n;
        double var = rs2[0] / n - mu * mu;
        double av  = (double)gamma[ch] / sqrt(var + 1e-5);
        a[ch] = (float)av;
        c[ch] = beta[ch] - (float)(mu * av);
    }
}

// ================= conv2: f32x2 packed, 12 ch/warp single pass, fused BN2 stats =================
__global__ void __launch_bounds__(256, 1)
k_conv2(const float* __restrict__ h1, const float* __restrict__ w2,
        const float* __restrict__ a1, const float* __restrict__ c1,
        float* __restrict__ h2, float* __restrict__ ps, float* __restrict__ psq) {
    extern __shared__ float smem[];
    float* sIn = smem;              // CE x 140
    float* sWT = smem + CE * 140;   // 264 x 96, row stride 96 (out-ch innermost)
    int b = blockIdx.x;
    int t0 = blockIdx.y * 128;
    int tid = threadIdx.x;
    int lane = tid & 31, wrp = tid >> 5;
    int oc0 = wrp * 12;

    for (int i = tid; i < CE * 140; i += 256) {
        int cc = i / 140, j = i - cc * 140;
        int gt = t0 + j;
        float v = 0.f;
        if (gt < T1) {
            v = h1[(b * CE + cc) * T1 + gt];
            v = fmaf(v, a1[cc], c1[cc]);
            v = v > 0.f ? v : expm1f(v);
        }
        sIn[i] = v;
    }
    for (int i = tid; i < D2 * 264; i += 256) {
        int och = i / 264, tap = i - och * 264;
        sWT[tap * D2 + och] = w2[i];
    }
    __syncthreads();

    unsigned long long acc[6][4];
#pragma unroll
    for (int p = 0; p < 6; p++)
#pragma unroll
        for (int tt = 0; tt < 4; tt++) acc[p][tt] = 0ull;

    for (int cc = 0; cc < CE; cc++) {
        const float* inr = sIn + cc * 140 + lane;
        const float* wr  = sWT + (cc * KW) * D2 + oc0;
#pragma unroll
        for (int k = 0; k < KW; k++) {
            unsigned long long xx[4];
#pragma unroll
            for (int tt = 0; tt < 4; tt++) xx[tt] = pack2(inr[32 * tt + k]);
            const float* wk_ = wr + k * D2;
#pragma unroll
            for (int p = 0; p < 6; p++) {
                unsigned long long wp = *(const unsigned long long*)(wk_ + 2 * p);
#pragma unroll
                for (int tt = 0; tt < 4; tt++) acc[p][tt] = ffma2(wp, xx[tt], acc[p][tt]);
            }
        }
    }

    int blk = b * 8 + blockIdx.y;
#pragma unroll
    for (int p = 0; p < 6; p++) {
        int ch0 = oc0 + 2 * p;
        float s0 = 0.f, q0 = 0.f, s1 = 0.f, q1 = 0.f;
#pragma unroll
        for (int tt = 0; tt < 4; tt++) {
            float lo, hi;
            unpack2(acc[p][tt], lo, hi);
            int t = t0 + lane + 32 * tt;
            if (t < T2) {
                h2[((size_t)b * D2 + ch0)     * T2 + t] = lo;
                h2[((size_t)b * D2 + ch0 + 1) * T2 + t] = hi;
                s0 += lo; q0 = fmaf(lo, lo, q0);
                s1 += hi; q1 = fmaf(hi, hi, q1);
            }
        }
#pragma unroll
        for (int off = 16; off > 0; off >>= 1) {
            s0 += __shfl_down_sync(0xffffffffu, s0, off);
            q0 += __shfl_down_sync(0xffffffffu, q0, off);
            s1 += __shfl_down_sync(0xffffffffu, s1, off);
            q1 += __shfl_down_sync(0xffffffffu, q1, off);
        }
        if (lane == 0) {
            ps [ch0 * NB2 + blk] = s0;  psq[ch0 * NB2 + blk] = q0;
            ps [(ch0 + 1) * NB2 + blk] = s1;  psq[(ch0 + 1) * NB2 + blk] = q1;
        }
    }
}

// ================= Gram: 2x2 tile per thread, f32x2 over t-pairs =================
__global__ void k_cov(const float* __restrict__ h2, const float* __restrict__ a2,
                      const float* __restrict__ c2, float* __restrict__ S) {
    __shared__ __align__(16) float sX[32 * 194];
    __shared__ float sa[32], sc[32];
    int bm = blockIdx.x;
    int b = bm / EP, m = bm - b * EP;
    int tid = threadIdx.x;              // 256
    int tx = tid & 15, ty = tid >> 4;
    if (tid < 32) {
        sa[tid] = a2[m * INS + tid];
        sc[tid] = c2[m * INS + tid];
    }
    unsigned long long a00 = 0, a01 = 0, a10 = 0, a11 = 0;
    for (int t0 = 0; t0 < T2; t0 += 192) {
        __syncthreads();
        for (int i = tid; i < 32 * 192; i += 256) {
            int r = i / 192, j = i - r * 192;
            int t = t0 + j;
            float v = 0.f;
            if (t < T2) {
                v = h2[((size_t)b * D2 + m * INS + r) * T2 + t];
                v = fmaf(v, sa[r], sc[r]);
                v = v > 0.f ? v : expm1f(v);
            }
            sX[r * 194 + j] = v;
        }
        __syncthreads();
        const float* rc0 = sX + ty * 194;
        const float* rc1 = sX + (ty + 16) * 194;
        const float* rd0 = sX + tx * 194;
        const float* rd1 = sX + (tx + 16) * 194;
#pragma unroll 4
        for (int j = 0; j < 192; j += 2) {
            unsigned long long xc0 = *(const unsigned long long*)(rc0 + j);
            unsigned long long xc1 = *(const unsigned long long*)(rc1 + j);
            unsigned long long xd0 = *(const unsigned long long*)(rd0 + j);
            unsigned long long xd1 = *(const unsigned long long*)(rd1 + j);
            a00 = ffma2(xc0, xd0, a00);
            a01 = ffma2(xc0, xd1, a01);
            a10 = ffma2(xc1, xd0, a10);
            a11 = ffma2(xc1, xd1, a11);
        }
    }
    float lo, hi;
    float* Sp = S + bm * (INS * INS);
    unpack2(a00, lo, hi); Sp[ty * 32 + tx]               = lo + hi;
    unpack2(a01, lo, hi); Sp[ty * 32 + tx + 16]          = lo + hi;
    unpack2(a10, lo, hi); Sp[(ty + 16) * 32 + tx]        = lo + hi;
    unpack2(a11, lo, hi); Sp[(ty + 16) * 32 + tx + 16]   = lo + hi;
}

// ================= parallel two-sided Jacobi, 32x32 symmetric, top-8 =================
__global__ void k_jacobi(const float* __restrict__ S, float* __restrict__ Up) {
    __shared__ float A[32][33], V[32][33];
    __shared__ float cs[16], sn[16];
    __shared__ int pps[16], qqs[16], sidx[8];
    int bm = blockIdx.x, tid = threadIdx.x;   // 256

    for (int i = tid; i < 1024; i += 256) {
        int r = i >> 5, cc = i & 31;
        A[r][cc] = S[bm * 1024 + i];
        V[r][cc] = (r == cc) ? 1.f : 0.f;
    }
    __syncthreads();

    int g = tid >> 4, l = tid & 15;
    for (int sw = 0; sw < NSWEEP; sw++) {
        for (int r = 0; r < 31; r++) {
            if (tid < 16) {
                int p = (tid == 0) ? 0 : ((tid - 1 + r) % 31) + 1;
                int q = ((30 - tid + r) % 31) + 1;
                if (p > q) { int tmp = p; p = q; q = tmp; }
                float app = A[p][p], aqq = A[q][q], apq = A[p][q];
                float cv = 1.f, sv = 0.f;
                if (fabsf(apq) > 1e-36f) {
                    float tau = (aqq - app) / (2.f * apq);
                    float tt = (tau >= 0.f ? 1.f : -1.f) / (fabsf(tau) + sqrtf(1.f + tau * tau));
                    cv = rsqrtf(1.f + tt * tt);
                    sv = tt * cv;
                }
                cs[tid] = cv; sn[tid] = sv; pps[tid] = p; qqs[tid] = q;
            }
            __syncthreads();
            {
                float cv = cs[g], sv = sn[g];
                int p = pps[g], q = qqs[g];
#pragma unroll
                for (int jj = l; jj < 32; jj += 16) {
                    float ap = A[p][jj], aq = A[q][jj];
                    A[p][jj] = cv * ap - sv * aq;
                    A[q][jj] = sv * ap + cv * aq;
                }
            }
            __syncthreads();
            {
                float cv = cs[g], sv = sn[g];
                int p = pps[g], q = qqs[g];
#pragma unroll
                for (int ii = l; ii < 32; ii += 16) {
                    float ap = A[ii][p], aq = A[ii][q];
                    A[ii][p] = cv * ap - sv * aq;
                    A[ii][q] = sv * ap + cv * aq;
                    float vp = V[ii][p], vq = V[ii][q];
                    V[ii][p] = cv * vp - sv * vq;
                    V[ii][q] = sv * vp + cv * vq;
                }
            }
            __syncthreads();
        }
    }

    if (tid == 0) {
        float vals[32];
        for (int i = 0; i < 32; i++) vals[i] = A[i][i];
        for (int j = 0; j < 8; j++) {
            int am = 0; float mv = vals[0];
            for (int i = 1; i < 32; i++) if (vals[i] > mv) { mv = vals[i]; am = i; }
            sidx[j] = am; vals[am] = -3.4e38f;
        }
    }
    __syncthreads();
    {
        int cc = tid >> 3, j = tid & 7;
        Up[bm * (INS * PP) + tid] = V[cc][sidx[j]];
    }
}

// ================= projectors via Cholesky =================
__global__ void k_proj(const float* __restrict__ Up, const float* __restrict__ wq,
                       const float* __restrict__ wk, const float* __restrict__ wv,
                       float* __restrict__ QQt, float* __restrict__ KKt,
                       float* __restrict__ Vp) {
    __shared__ float sUp[32][8], sM[16][8], sG[8][8], sY[16][8];
    int bm = blockIdx.x, tid = threadIdx.x;   // 128
    int b = bm / EP, m = bm - b * EP;
    for (int i = tid; i < 256; i += 128) sUp[i >> 3][i & 7] = Up[bm * 256 + i];

    int nmat = (m == 2) ? 3 : 2;
    for (int mat = 0; mat < nmat; mat++) {
        const float* W = (mat == 0) ? wq : (mat == 1) ? wk : wv;
        __syncthreads();
        {
            int r = tid >> 3, p = tid & 7;
            float s = 0.f;
            for (int cc = 0; cc < 32; cc++) s = fmaf(W[r * 32 + cc], sUp[cc][p], s);
            sM[r][p] = s;
        }
        __syncthreads();
        if (tid < 64) {
            int i = tid >> 3, j = tid & 7;
            float s = 0.f;
            for (int rr = 0; rr < 16; rr++) s = fmaf(sM[rr][i], sM[rr][j], s);
            sG[i][j] = s;
        }
        __syncthreads();
        if (tid == 0) {
            for (int k = 0; k < 8; k++) {
                float lkk = sqrtf(sG[k][k]);
                sG[k][k] = lkk;
                float inv = 1.f / lkk;
                for (int i = k + 1; i < 8; i++) sG[i][k] *= inv;
                for (int j = k + 1; j < 8; j++)
                    for (int i = j; i < 8; i++) sG[i][j] -= sG[i][k] * sG[j][k];
            }
        }
        __syncthreads();
        if (tid < 16) {
            int r = tid;
            for (int i = 0; i < 8; i++) {
                float v = sM[r][i];
                for (int j = 0; j < i; j++) v -= sG[i][j] * sY[r][j];
                sY[r][i] = v / sG[i][i];
            }
        }
        __syncthreads();
        float* outp = (mat == 0) ? (QQt + bm * 256)
                    : (mat == 1) ? (KKt + bm * 256)
                                 : (Vp + b * 256);
        for (int e = tid; e < 256; e += 128) {
            int u = e >> 4, v = e & 15;
            float s = 0.f;
#pragma unroll
            for (int i = 0; i < 8; i++) s = fmaf(sY[u][i], sY[v][i], s);
            outp[e] = s;
        }
    }
}

// ================= E, softmax weights, final linear =================
__global__ void k_final(const float* __restrict__ QQt, const float* __restrict__ KKt,
                        const float* __restrict__ Vp, const float* __restrict__ lw,
                        const float* __restrict__ lb, float* __restrict__ out) {
    int b = blockIdx.x, tid = threadIdx.x;    // 256
    __shared__ float sQ[3 * 256], sK[3 * 256], sV[256];
    __shared__ float sE[9], swv[3];
    __shared__ float red[8];
    __shared__ float red12[12][8];
    for (int i = tid; i < 768; i += 256) {
        sQ[i] = QQt[b * 768 + i];
        sK[i] = KKt[b * 768 + i];
    }
    sV[tid] = Vp[b * 256 + tid];
    __syncthreads();

    int u = tid >> 4, v = tid & 15;
    for (int ij = 0; ij < 9; ij++) {
        int i = ij / 3, j = ij - 3 * i;
        const float* Qj = sQ + j * 256;
        const float* Ki = sK + i * 256;
        float dd = 0.f;
#pragma unroll
        for (int w = 0; w < 16; w++) {
            float du = Qj[u * 16 + w] - Ki[u * 16 + w];
            float dv = Qj[v * 16 + w] - Ki[v * 16 + w];
            dd = fmaf(du, dv, dd);
        }
        float val = dd * dd;
        for (int off = 16; off > 0; off >>= 1) val += __shfl_down_sync(0xffffffffu, val, off);
        if ((tid & 31) == 0) red[tid >> 5] = val;
        __syncthreads();
        if (tid == 0) {
            float s = 0.f;
            for (int w = 0; w < 8; w++) s += red[w];
            sE[ij] = sqrtf(s);
        }
        __syncthreads();
    }
    if (tid == 0) {
        for (int j = 0; j < 3; j++) {
            float s0 = 1.f / (1.f + log1pf(sE[0 * 3 + j]));
            float s1 = 1.f / (1.f + log1pf(sE[1 * 3 + j]));
            float s2 = 1.f / (1.f + log1pf(sE[2 * 3 + j]));
            float mx = fmaxf(s0, fmaxf(s1, s2));
            float e0 = expf(s0 - mx), e1 = expf(s1 - mx), e2 = expf(s2 - mx);
            swv[j] = e2 / (e0 + e1 + e2);
        }
    }
    __syncthreads();

    float vv = sV[tid];
    float part[12];
#pragma unroll
    for (int r = 0; r < 4; r++)
#pragma unroll
        for (int j = 0; j < 3; j++)
            part[r * 3 + j] = lw[r * 768 + j * 256 + tid] * vv;
#pragma unroll
    for (int kk = 0; kk < 12; kk++) {
        float val = part[kk];
        for (int off = 16; off > 0; off >>= 1) val += __shfl_down_sync(0xffffffffu, val, off);
        if ((tid & 31) == 0) red12[kk][tid >> 5] = val;
    }
    __syncthreads();
    if (tid < 4) {
        float o = lb[tid];
        for (int j = 0; j < 3; j++) {
            float ds = 0.f;
            for (int w = 0; w < 8; w++) ds += red12[tid * 3 + j][w];
            o = fmaf(swv[j], ds, o);
        }
        out[b * 4 + tid] = o;
    }
}

// ================= launch =================
extern "C" void kernel_launch(void* const* d_in, const int* in_sizes, int n_in,
                              void* d_out, int out_size) {
    const float* x      = (const float*)d_in[0];
    const float* conv1w = (const float*)d_in[1];
    const float* bn1g   = (const float*)d_in[3];
    const float* bn1b   = (const float*)d_in[4];
    const float* conv2w = (const float*)d_in[5];
    const float* bn2g   = (const float*)d_in[7];
    const float* bn2b   = (const float*)d_in[8];
    const float* wq     = (const float*)d_in[9];
    const float* wk     = (const float*)d_in[10];
    const float* wv     = (const float*)d_in[11];
    const float* linw   = (const float*)d_in[12];
    const float* linb   = (const float*)d_in[13];
    float* out = (float*)d_out;

    float *h1, *h2, *a1, *c1, *a2, *c2, *S, *Up, *QQt, *KKt, *Vp;
    float *ps1, *ps1q, *ps2, *ps2q;
    cudaGetSymbolAddress((void**)&h1,  g_h1);
    cudaGetSymbolAddress((void**)&h2,  g_h2);
    cudaGetSymbolAddress((void**)&a1,  g_a1);
    cudaGetSymbolAddress((void**)&c1,  g_c1);
    cudaGetSymbolAddress((void**)&a2,  g_a2);
    cudaGetSymbolAddress((void**)&c2,  g_c2);
    cudaGetSymbolAddress((void**)&S,   g_S);
    cudaGetSymbolAddress((void**)&Up,  g_Up);
    cudaGetSymbolAddress((void**)&QQt, g_QQt);
    cudaGetSymbolAddress((void**)&KKt, g_KKt);
    cudaGetSymbolAddress((void**)&Vp,  g_Vp);
    cudaGetSymbolAddress((void**)&ps1, g_ps1);
    cudaGetSymbolAddress((void**)&ps1q,g_ps1q);
    cudaGetSymbolAddress((void**)&ps2, g_ps2);
    cudaGetSymbolAddress((void**)&ps2q,g_ps2q);

    const int SMEM2 = (CE * 140 + 264 * D2) * sizeof(float);   // ~113.7 KB
    static bool attr_done = false;
    cudaFuncSetAttribute(k_conv2, cudaFuncAttributeMaxDynamicSharedMemorySize, SMEM2);
    (void)attr_done;

    k_conv1 <<<NB1, 256>>>(x, conv1w, h1, ps1, ps1q);
    k_fin   <<<CE, 256>>>(ps1, ps1q, bn1g, bn1b, a1, c1, NB1, (double)BS * T1);
    k_conv2 <<<dim3(BS, 8), 256, SMEM2>>>(h1, conv2w, a1, c1, h2, ps2, ps2q);
    k_fin   <<<D2, 256>>>(ps2, ps2q, bn2g, bn2b, a2, c2, NB2, (double)BS * T2);
    k_cov   <<<BS * EP, 256>>>(h2, a2, c2, S);
    k_jacobi<<<BS * EP, 256>>>(S, Up);
    k_proj  <<<BS * EP, 128>>>(Up, wq, wk, wv, QQt, KKt, Vp);
    k_final <<<BS, 256>>>(QQt, KKt, Vp, linw, linb, out);
}

// round 4
// speedup vs baseline: 2.1451x; 1.2932x over previous
#include <cuda_runtime.h>
#include <cuda_bf16.h>
#include <math.h>

// ---------------- problem constants ----------------
#define BS     256
#define CE     22
#define T1     1000
#define D2     96
#define KW     12
#define T2     989
#define T2P    992     // padded h2 stride (16B-aligned rows)
#define EP     3
#define INS    32
#define PP     8
#define OUTS   16
#define NSWEEP 8
#define NB1    500
#define NB2    2048

typedef unsigned long long ull;

// ---------------- scratch ----------------
__device__ float g_h1[BS * CE * T1];
__device__ float g_h2[(size_t)BS * D2 * T2P];
__device__ float g_a1[CE],  g_c1[CE];
__device__ float g_a2[D2],  g_c2[D2];
__device__ float g_S [BS * EP * INS * INS];
__device__ float g_Up[BS * EP * INS * PP];
__device__ float g_QQt[BS * EP * OUTS * OUTS];
__device__ float g_KKt[BS * EP * OUTS * OUTS];
__device__ float g_Vp [BS * OUTS * OUTS];
__device__ float g_ps1 [CE * NB1], g_ps1q[CE * NB1];
__device__ float g_ps2 [D2 * NB2], g_ps2q[D2 * NB2];

// ---------------- f32x2 helpers ----------------
__device__ __forceinline__ ull ffma2(ull a, ull b, ull c) {
    ull d;
    asm("fma.rn.f32x2 %0, %1, %2, %3;" : "=l"(d) : "l"(a), "l"(b), "l"(c));
    return d;
}
__device__ __forceinline__ ull pack2(float x) {
    ull r;
    asm("mov.b64 %0, {%1, %1};" : "=l"(r) : "f"(x));
    return r;
}
__device__ __forceinline__ ull pack2p(float a, float b) {
    ull r;
    asm("mov.b64 %0, {%1, %2};" : "=l"(r) : "f"(a), "f"(b));
    return r;
}
__device__ __forceinline__ void unpack2(ull v, float& lo, float& hi) {
    asm("mov.b64 {%0, %1}, %2;" : "=f"(lo), "=f"(hi) : "l"(v));
}

// ================= conv1: f32x2, 4 t/thread, fused BN1 partials =================
__global__ void __launch_bounds__(128) k_conv1(
        const float* __restrict__ x, const float* __restrict__ w1,
        float* __restrict__ h1, float* __restrict__ ps, float* __restrict__ psq) {
    __shared__ float sW[CE * CE];
    __shared__ float wb[CE][4], wb2[CE][4];
    int tid = threadIdx.x, lane = tid & 31, wrp = tid >> 5;
    for (int i = tid; i < CE * CE; i += 128) sW[i] = w1[i];
    __syncthreads();
    int idx = blockIdx.x * 128 + tid;          // BS*250 threads
    int b = idx / 250, t0 = (idx - b * 250) * 4;

    ull xv[CE][2];
#pragma unroll
    for (int c = 0; c < CE; c++) {
        float4 q = *(const float4*)(x + (b * CE + c) * T1 + t0);
        xv[c][0] = pack2p(q.x, q.y);
        xv[c][1] = pack2p(q.z, q.w);
    }
#pragma unroll
    for (int o = 0; o < CE; o++) {
        ull s0 = 0ull, s1 = 0ull;
#pragma unroll
        for (int c = 0; c < CE; c++) {
            ull wv = pack2(sW[o * CE + c]);
            s0 = ffma2(wv, xv[c][0], s0);
            s1 = ffma2(wv, xv[c][1], s1);
        }
        float a0, a1v, a2v, a3;
        unpack2(s0, a0, a1v); unpack2(s1, a2v, a3);
        float4 o4 = make_float4(a0, a1v, a2v, a3);
        *(float4*)(h1 + (b * CE + o) * T1 + t0) = o4;
        float sm = a0 + a1v + a2v + a3;
        float sq = a0 * a0 + a1v * a1v + a2v * a2v + a3 * a3;
#pragma unroll
        for (int off = 16; off > 0; off >>= 1) {
            sm += __shfl_down_sync(0xffffffffu, sm, off);
            sq += __shfl_down_sync(0xffffffffu, sq, off);
        }
        if (lane == 0) { wb[o][wrp] = sm; wb2[o][wrp] = sq; }
    }
    __syncthreads();
    if (tid < CE) {
        float a = 0.f, bq = 0.f;
#pragma unroll
        for (int w = 0; w < 4; w++) { a += wb[tid][w]; bq += wb2[tid][w]; }
        ps [tid * NB1 + blockIdx.x] = a;
        psq[tid * NB1 + blockIdx.x] = bq;
    }
}

// ================= finalize BN =================
__global__ void k_fin(const float* __restrict__ ps, const float* __restrict__ psq,
                      const float* __restrict__ gamma, const float* __restrict__ beta,
                      float* __restrict__ a, float* __restrict__ c,
                      int NB, double n) {
    int ch = blockIdx.x, tid = threadIdx.x;
    double s = 0.0, s2 = 0.0;
    for (int i = tid; i < NB; i += 256) {
        s  += (double)ps [ch * NB + i];
        s2 += (double)psq[ch * NB + i];
    }
    __shared__ double rs[256], rs2[256];
    rs[tid] = s; rs2[tid] = s2;
    __syncthreads();
    for (int off = 128; off > 0; off >>= 1) {
        if (tid < off) { rs[tid] += rs[tid + off]; rs2[tid] += rs2[tid + off]; }
        __syncthreads();
    }
    if (tid == 0) {
        double mu  = rs[0] / n;
        double var = rs2[0] / n - mu * mu;
        double av  = (double)gamma[ch] / sqrt(var + 1e-5);
        a[ch] = (float)av;
        c[ch] = beta[ch] - (float)(mu * av);
    }
}

// ================= conv2: 48 ch/block, register x-window, f32x2 =================
// grid (BS, 8, 2); block 256 thr; warp = 6 out-ch x 128 t (4 t per lane)
#define IN_STR 144
__global__ void __launch_bounds__(256) k_conv2(
        const float* __restrict__ h1, const float* __restrict__ w2,
        const float* __restrict__ a1, const float* __restrict__ c1,
        float* __restrict__ h2, float* __restrict__ ps, float* __restrict__ psq) {
    extern __shared__ float smem[];
    float* sIn = smem;                 // CE x IN_STR
    float* sWT = smem + CE * IN_STR;   // 264 taps x 48 ch (ch innermost)
    int b = blockIdx.x, by = blockIdx.y, bz = blockIdx.z;
    int t0 = by * 128;
    int tid = threadIdx.x, lane = tid & 31, wrp = tid >> 5;

    for (int i = tid; i < CE * IN_STR; i += 256) {
        int cc = i / IN_STR, j = i - cc * IN_STR;
        int gt = t0 + j;
        float v = 0.f;
        if (j < 139 && gt < T1) {
            v = h1[(b * CE + cc) * T1 + gt];
            v = fmaf(v, a1[cc], c1[cc]);
            v = v > 0.f ? v : expm1f(v);
        }
        sIn[i] = v;
    }
    for (int i = tid; i < 48 * 264; i += 256) {
        int chl = i / 264, tap = i - chl * 264;
        sWT[tap * 48 + chl] = w2[((size_t)(bz * 48 + chl)) * 264 + tap];
    }
    __syncthreads();

    int ocl = wrp * 6;
    int tb  = 4 * lane;
    ull acc[3][4];
#pragma unroll
    for (int p = 0; p < 3; p++)
#pragma unroll
        for (int tt = 0; tt < 4; tt++) acc[p][tt] = 0ull;

    for (int cc = 0; cc < CE; cc++) {
        const float4* p4 = (const float4*)(sIn + cc * IN_STR + tb);
        float4 q0 = p4[0], q1 = p4[1], q2 = p4[2], q3 = p4[3];
        float xw[16] = {q0.x, q0.y, q0.z, q0.w, q1.x, q1.y, q1.z, q1.w,
                        q2.x, q2.y, q2.z, q2.w, q3.x, q3.y, q3.z, q3.w};
        const float* wbase = sWT + (cc * KW) * 48 + ocl;
#pragma unroll
        for (int k = 0; k < KW; k++) {
            ull x0 = pack2(xw[k]), x1 = pack2(xw[k + 1]);
            ull x2 = pack2(xw[k + 2]), x3 = pack2(xw[k + 3]);
            const float* wk_ = wbase + k * 48;
#pragma unroll
            for (int p = 0; p < 3; p++) {
                ull wp = *(const ull*)(wk_ + 2 * p);
                acc[p][0] = ffma2(wp, x0, acc[p][0]);
                acc[p][1] = ffma2(wp, x1, acc[p][1]);
                acc[p][2] = ffma2(wp, x2, acc[p][2]);
                acc[p][3] = ffma2(wp, x3, acc[p][3]);
            }
        }
    }

    int blk = b * 8 + by;
    int tg  = t0 + tb;                       // global t of tt=0
    int nv  = T2 - tg; nv = nv < 0 ? 0 : (nv > 4 ? 4 : nv);
#pragma unroll
    for (int p = 0; p < 3; p++) {
        int ch0 = bz * 48 + ocl + 2 * p;
        float lo[4], hi[4];
#pragma unroll
        for (int tt = 0; tt < 4; tt++) unpack2(acc[p][tt], lo[tt], hi[tt]);
        float* r0 = h2 + ((size_t)b * D2 + ch0) * T2P + tg;
        float* r1 = r0 + T2P;
        if (nv == 4) {
            *(float4*)r0 = make_float4(lo[0], lo[1], lo[2], lo[3]);
            *(float4*)r1 = make_float4(hi[0], hi[1], hi[2], hi[3]);
        } else {
            for (int tt = 0; tt < nv; tt++) { r0[tt] = lo[tt]; r1[tt] = hi[tt]; }
        }
        float s0 = 0.f, q0 = 0.f, s1 = 0.f, q1 = 0.f;
#pragma unroll
        for (int tt = 0; tt < 4; tt++) {
            if (tt < nv) {
                s0 += lo[tt]; q0 = fmaf(lo[tt], lo[tt], q0);
                s1 += hi[tt]; q1 = fmaf(hi[tt], hi[tt], q1);
            }
        }
#pragma unroll
        for (int off = 16; off > 0; off >>= 1) {
            s0 += __shfl_down_sync(0xffffffffu, s0, off);
            q0 += __shfl_down_sync(0xffffffffu, q0, off);
            s1 += __shfl_down_sync(0xffffffffu, s1, off);
            q1 += __shfl_down_sync(0xffffffffu, q1, off);
        }
        if (lane == 0) {
            ps [(size_t)ch0 * NB2 + blk]       = s0;
            psq[(size_t)ch0 * NB2 + blk]       = q0;
            ps [(size_t)(ch0 + 1) * NB2 + blk] = s1;
            psq[(size_t)(ch0 + 1) * NB2 + blk] = q1;
        }
    }
}

// ================= Gram: 2x2 tile, f32x2 over t-pairs =================
__global__ void k_cov(const float* __restrict__ h2, const float* __restrict__ a2,
                      const float* __restrict__ c2, float* __restrict__ S) {
    __shared__ __align__(16) float sX[32 * 194];
    __shared__ float sa[32], sc[32];
    int bm = blockIdx.x;
    int b = bm / EP, m = bm - b * EP;
    int tid = threadIdx.x;              // 256
    int tx = tid & 15, ty = tid >> 4;
    if (tid < 32) {
        sa[tid] = a2[m * INS + tid];
        sc[tid] = c2[m * INS + tid];
    }
    ull a00 = 0, a01 = 0, a10 = 0, a11 = 0;
    for (int t0 = 0; t0 < T2; t0 += 192) {
        __syncthreads();
        for (int i = tid; i < 32 * 192; i += 256) {
            int r = i / 192, j = i - r * 192;
            int t = t0 + j;
            float v = 0.f;
            if (t < T2) {
                v = h2[((size_t)b * D2 + m * INS + r) * T2P + t];
                v = fmaf(v, sa[r], sc[r]);
                v = v > 0.f ? v : expm1f(v);
            }
            sX[r * 194 + j] = v;
        }
        __syncthreads();
        const float* rc0 = sX + ty * 194;
        const float* rc1 = sX + (ty + 16) * 194;
        const float* rd0 = sX + tx * 194;
        const float* rd1 = sX + (tx + 16) * 194;
#pragma unroll 4
        for (int j = 0; j < 192; j += 2) {
            ull xc0 = *(const ull*)(rc0 + j);
            ull xc1 = *(const ull*)(rc1 + j);
            ull xd0 = *(const ull*)(rd0 + j);
            ull xd1 = *(const ull*)(rd1 + j);
            a00 = ffma2(xc0, xd0, a00);
            a01 = ffma2(xc0, xd1, a01);
            a10 = ffma2(xc1, xd0, a10);
            a11 = ffma2(xc1, xd1, a11);
        }
    }
    float lo, hi;
    float* Sp = S + bm * (INS * INS);
    unpack2(a00, lo, hi); Sp[ty * 32 + tx]             = lo + hi;
    unpack2(a01, lo, hi); Sp[ty * 32 + tx + 16]        = lo + hi;
    unpack2(a10, lo, hi); Sp[(ty + 16) * 32 + tx]      = lo + hi;
    unpack2(a11, lo, hi); Sp[(ty + 16) * 32 + tx + 16] = lo + hi;
}

// ================= Jacobi: 2 barriers/round, redundant per-group rotations =================
__global__ void k_jacobi(const float* __restrict__ S, float* __restrict__ Up) {
    __shared__ float A[32][33], V[32][33];
    __shared__ int sidx[8];
    int bm = blockIdx.x, tid = threadIdx.x;   // 256

    for (int i = tid; i < 1024; i += 256) {
        int r = i >> 5, cc = i & 31;
        A[r][cc] = S[bm * 1024 + i];
        V[r][cc] = (r == cc) ? 1.f : 0.f;
    }
    __syncthreads();

    int g = tid >> 4, l = tid & 15;
    for (int sw = 0; sw < NSWEEP; sw++) {
        for (int r = 0; r < 31; r++) {
            int p = (g == 0) ? 0 : ((g - 1 + r) % 31) + 1;
            int q = ((30 - g + r) % 31) + 1;
            if (p > q) { int tmp = p; p = q; q = tmp; }
            // every thread of the group computes its rotation (no handoff barrier)
            float app = A[p][p], aqq = A[q][q], apq = A[p][q];
            float cv = 1.f, sv = 0.f;
            if (fabsf(apq) > 1e-36f) {
                float tau = (aqq - app) / (2.f * apq);
                float tt = (tau >= 0.f ? 1.f : -1.f) / (fabsf(tau) + sqrtf(1.f + tau * tau));
                cv = rsqrtf(1.f + tt * tt);
                sv = tt * cv;
            }
            // row phase (rows p,q disjoint across groups)
            {
                float ap = A[p][l], aq = A[q][l];
                A[p][l] = cv * ap - sv * aq;
                A[q][l] = sv * ap + cv * aq;
                int j1 = l + 16;
                ap = A[p][j1]; aq = A[q][j1];
                A[p][j1] = cv * ap - sv * aq;
                A[q][j1] = sv * ap + cv * aq;
            }
            __syncthreads();
            // col phase (cols p,q disjoint across groups) + V
            {
#pragma unroll
                for (int s = 0; s < 2; s++) {
                    int ii = l + 16 * s;
                    float ap = A[ii][p], aq = A[ii][q];
                    A[ii][p] = cv * ap - sv * aq;
                    A[ii][q] = sv * ap + cv * aq;
                    float vp = V[ii][p], vq = V[ii][q];
                    V[ii][p] = cv * vp - sv * vq;
                    V[ii][q] = sv * vp + cv * vq;
                }
            }
            __syncthreads();
        }
    }

    if (tid == 0) {
        float vals[32];
        for (int i = 0; i < 32; i++) vals[i] = A[i][i];
        for (int j = 0; j < 8; j++) {
            int am = 0; float mv = vals[0];
            for (int i = 1; i < 32; i++) if (vals[i] > mv) { mv = vals[i]; am = i; }
            sidx[j] = am; vals[am] = -3.4e38f;
        }
    }
    __syncthreads();
    {
        int cc = tid >> 3, j = tid & 7;
        Up[bm * (INS * PP) + tid] = V[cc][sidx[j]];
    }
}

// ================= projectors via Cholesky =================
__global__ void k_proj(const float* __restrict__ Up, const float* __restrict__ wq,
                       const float* __restrict__ wk, const float* __restrict__ wv,
                       float* __restrict__ QQt, float* __restrict__ KKt,
                       float* __restrict__ Vp) {
    __shared__ float sUp[32][8], sM[16][8], sG[8][8], sY[16][8];
    int bm = blockIdx.x, tid = threadIdx.x;   // 128
    int b = bm / EP, m = bm - b * EP;
    for (int i = tid; i < 256; i += 128) sUp[i >> 3][i & 7] = Up[bm * 256 + i];

    int nmat = (m == 2) ? 3 : 2;
    for (int mat = 0; mat < nmat; mat++) {
        const float* W = (mat == 0) ? wq : (mat == 1) ? wk : wv;
        __syncthreads();
        {
            int r = tid >> 3, p = tid & 7;
            float s = 0.f;
            for (int cc = 0; cc < 32; cc++) s = fmaf(W[r * 32 + cc], sUp[cc][p], s);
            sM[r][p] = s;
        }
        __syncthreads();
        if (tid < 64) {
            int i = tid >> 3, j = tid & 7;
            float s = 0.f;
            for (int rr = 0; rr < 16; rr++) s = fmaf(sM[rr][i], sM[rr][j], s);
            sG[i][j] = s;
        }
        __syncthreads();
        if (tid == 0) {
            for (int k = 0; k < 8; k++) {
                float lkk = sqrtf(sG[k][k]);
                sG[k][k] = lkk;
                float inv = 1.f / lkk;
                for (int i = k + 1; i < 8; i++) sG[i][k] *= inv;
                for (int j = k + 1; j < 8; j++)
                    for (int i = j; i < 8; i++) sG[i][j] -= sG[i][k] * sG[j][k];
            }
        }
        __syncthreads();
        if (tid < 16) {
            int r = tid;
            for (int i = 0; i < 8; i++) {
                float v = sM[r][i];
                for (int j = 0; j < i; j++) v -= sG[i][j] * sY[r][j];
                sY[r][i] = v / sG[i][i];
            }
        }
        __syncthreads();
        float* outp = (mat == 0) ? (QQt + bm * 256)
                    : (mat == 1) ? (KKt + bm * 256)
                                 : (Vp + b * 256);
        for (int e = tid; e < 256; e += 128) {
            int u = e >> 4, v = e & 15;
            float s = 0.f;
#pragma unroll
            for (int i = 0; i < 8; i++) s = fmaf(sY[u][i], sY[v][i], s);
            outp[e] = s;
        }
    }
}

// ================= E, softmax, final linear =================
__global__ void k_final(const float* __restrict__ QQt, const float* __restrict__ KKt,
                        const float* __restrict__ Vp, const float* __restrict__ lw,
                        const float* __restrict__ lb, float* __restrict__ out) {
    int b = blockIdx.x, tid = threadIdx.x;    // 256
    __shared__ float sQ[3 * 256], sK[3 * 256], sV[256];
    __shared__ float sE[9], swv[3];
    __shared__ float red[8];
    __shared__ float red12[12][8];
    for (int i = tid; i < 768; i += 256) {
        sQ[i] = QQt[b * 768 + i];
        sK[i] = KKt[b * 768 + i];
    }
    sV[tid] = Vp[b * 256 + tid];
    __syncthreads();

    int u = tid >> 4, v = tid & 15;
    for (int ij = 0; ij < 9; ij++) {
        int i = ij / 3, j = ij - 3 * i;
        const float* Qj = sQ + j * 256;
        const float* Ki = sK + i * 256;
        float dd = 0.f;
#pragma unroll
        for (int w = 0; w < 16; w++) {
            float du = Qj[u * 16 + w] - Ki[u * 16 + w];
            float dv = Qj[v * 16 + w] - Ki[v * 16 + w];
            dd = fmaf(du, dv, dd);
        }
        float val = dd * dd;
        for (int off = 16; off > 0; off >>= 1) val += __shfl_down_sync(0xffffffffu, val, off);
        if ((tid & 31) == 0) red[tid >> 5] = val;
        __syncthreads();
        if (tid == 0) {
            float s = 0.f;
            for (int w = 0; w < 8; w++) s += red[w];
            sE[ij] = sqrtf(s);
        }
        __syncthreads();
    }
    if (tid == 0) {
        for (int j = 0; j < 3; j++) {
            float s0 = 1.f / (1.f + log1pf(sE[0 * 3 + j]));
            float s1 = 1.f / (1.f + log1pf(sE[1 * 3 + j]));
            float s2 = 1.f / (1.f + log1pf(sE[2 * 3 + j]));
            float mx = fmaxf(s0, fmaxf(s1, s2));
            float e0 = expf(s0 - mx), e1 = expf(s1 - mx), e2 = expf(s2 - mx);
            swv[j] = e2 / (e0 + e1 + e2);
        }
    }
    __syncthreads();

    float vv = sV[tid];
    float part[12];
#pragma unroll
    for (int r = 0; r < 4; r++)
#pragma unroll
        for (int j = 0; j < 3; j++)
            part[r * 3 + j] = lw[r * 768 + j * 256 + tid] * vv;
#pragma unroll
    for (int kk = 0; kk < 12; kk++) {
        float val = part[kk];
        for (int off = 16; off > 0; off >>= 1) val += __shfl_down_sync(0xffffffffu, val, off);
        if ((tid & 31) == 0) red12[kk][tid >> 5] = val;
    }
    __syncthreads();
    if (tid < 4) {
        float o = lb[tid];
        for (int j = 0; j < 3; j++) {
            float ds = 0.f;
            for (int w = 0; w < 8; w++) ds += red12[tid * 3 + j][w];
            o = fmaf(swv[j], ds, o);
        }
        out[b * 4 + tid] = o;
    }
}

// ================= launch =================
extern "C" void kernel_launch(void* const* d_in, const int* in_sizes, int n_in,
                              void* d_out, int out_size) {
    const float* x      = (const float*)d_in[0];
    const float* conv1w = (const float*)d_in[1];
    const float* bn1g   = (const float*)d_in[3];
    const float* bn1b   = (const float*)d_in[4];
    const float* conv2w = (const float*)d_in[5];
    const float* bn2g   = (const float*)d_in[7];
    const float* bn2b   = (const float*)d_in[8];
    const float* wq     = (const float*)d_in[9];
    const float* wk     = (const float*)d_in[10];
    const float* wv     = (const float*)d_in[11];
    const float* linw   = (const float*)d_in[12];
    const float* linb   = (const float*)d_in[13];
    float* out = (float*)d_out;

    float *h1, *h2, *a1, *c1, *a2, *c2, *S, *Up, *QQt, *KKt, *Vp;
    float *ps1, *ps1q, *ps2, *ps2q;
    cudaGetSymbolAddress((void**)&h1,  g_h1);
    cudaGetSymbolAddress((void**)&h2,  g_h2);
    cudaGetSymbolAddress((void**)&a1,  g_a1);
    cudaGetSymbolAddress((void**)&c1,  g_c1);
    cudaGetSymbolAddress((void**)&a2,  g_a2);
    cudaGetSymbolAddress((void**)&c2,  g_c2);
    cudaGetSymbolAddress((void**)&S,   g_S);
    cudaGetSymbolAddress((void**)&Up,  g_Up);
    cudaGetSymbolAddress((void**)&QQt, g_QQt);
    cudaGetSymbolAddress((void**)&KKt, g_KKt);
    cudaGetSymbolAddress((void**)&Vp,  g_Vp);
    cudaGetSymbolAddress((void**)&ps1, g_ps1);
    cudaGetSymbolAddress((void**)&ps1q,g_ps1q);
    cudaGetSymbolAddress((void**)&ps2, g_ps2);
    cudaGetSymbolAddress((void**)&ps2q,g_ps2q);

    const int SMEM2 = (CE * IN_STR + 264 * 48) * sizeof(float);   // 63,360 B
    cudaFuncSetAttribute(k_conv2, cudaFuncAttributeMaxDynamicSharedMemorySize, SMEM2);

    k_conv1 <<<NB1, 128>>>(x, conv1w, h1, ps1, ps1q);
    k_fin   <<<CE, 256>>>(ps1, ps1q, bn1g, bn1b, a1, c1, NB1, (double)BS * T1);
    k_conv2 <<<dim3(BS, 8, 2), 256, SMEM2>>>(h1, conv2w, a1, c1, h2, ps2, ps2q);
    k_fin   <<<D2, 256>>>(ps2, ps2q, bn2g, bn2b, a2, c2, NB2, (double)BS * T2);
    k_cov   <<<BS * EP, 256>>>(h2, a2, c2, S);
    k_jacobi<<<BS * EP, 256>>>(S, Up);
    k_proj  <<<BS * EP, 128>>>(Up, wq, wk, wv, QQt, KKt, Vp);
    k_final <<<BS, 256>>>(QQt, KKt, Vp, linw, linb, out);
}